// round 3
// baseline (speedup 1.0000x reference)
#include <cuda_runtime.h>

#define N_  2
#define C_  64
#define H_  256
#define W_  256
#define HW  (H_*W_)
#define HD  128
#define WD  128
#define HWD (HD*WD)
#define KK  25

// scratch (allocation-free rule: device globals)
__device__ float g_down[N_*C_*HW];        // 33.5 MB
__device__ float g_k[N_*HD*WD*KK];        //  3.3 MB  layout (n, hd, wd, kk)
__device__ float g_reasm[N_*256*HWD];     // 33.5 MB  layout (n, c2, hd, wd)

// ---------------------------------------------------------------------------
// Kernel 1: 1x1 conv 64->64 over (N,64,256,256). GEMM per 64-pixel tile.
// 256 threads, 4x4 register tile per thread.
// ---------------------------------------------------------------------------
__global__ void k_down(const float* __restrict__ x,
                       const float* __restrict__ w,
                       const float* __restrict__ b) {
    __shared__ float Xs[64][65];   // [cin][pixel]
    __shared__ float Ws[64][65];   // [cin][cout]
    const int tid = threadIdx.x;
    const int n  = blockIdx.x >> 10;            // 1024 blocks per n
    const int p0 = (blockIdx.x & 1023) << 6;    // 64 pixels per block

#pragma unroll
    for (int i = 0; i < 16; i++) {
        int idx = tid + i * 256;
        int r = idx >> 6, cc = idx & 63;
        Xs[r][cc] = x[(n * C_ + r) * HW + p0 + cc];   // coalesced
        Ws[cc][r] = w[r * 64 + cc];                   // w[cout][cin] -> Ws[cin][cout]
    }
    __syncthreads();

    const int px = tid & 15;   // pixel group
    const int ch = tid >> 4;   // channel group
    float acc[4][4];
#pragma unroll
    for (int j = 0; j < 4; j++) {
        float bv = b[ch + 16 * j];
#pragma unroll
        for (int i = 0; i < 4; i++) acc[i][j] = bv;
    }

#pragma unroll 8
    for (int kc = 0; kc < 64; kc++) {
        float xv[4], wv[4];
#pragma unroll
        for (int i = 0; i < 4; i++) xv[i] = Xs[kc][px + 16 * i];
#pragma unroll
        for (int j = 0; j < 4; j++) wv[j] = Ws[kc][ch + 16 * j];
#pragma unroll
        for (int i = 0; i < 4; i++)
#pragma unroll
            for (int j = 0; j < 4; j++) acc[i][j] += xv[i] * wv[j];
    }

#pragma unroll
    for (int j = 0; j < 4; j++)
#pragma unroll
        for (int i = 0; i < 4; i++)
            g_down[(n * C_ + ch + 16 * j) * HW + p0 + px + 16 * i] = acc[i][j];
}

// ---------------------------------------------------------------------------
// Kernel 2: 3x3 stride-2 conv (64ch -> 25 logits) + softmax, fused.
// Block: 16 wd x 16 hd tile, 128 threads, each thread owns 2 hd rows.
// Writes k transposed: g_k[n][hd][wd][kk].
// ---------------------------------------------------------------------------
__global__ void k_enc(const float* __restrict__ ew,
                      const float* __restrict__ eb) {
    __shared__ float tile[33][36];
    __shared__ float ws[25][9];
    const int n   = blockIdx.z;
    const int hd0 = blockIdx.y * 16;
    const int wd0 = blockIdx.x * 16;
    const int tid = threadIdx.x;           // 128
    const int tx  = tid & 15;              // wd within tile
    const int ty  = tid >> 4;              // 0..7 -> hd pair

    float acc0[KK], acc1[KK];
#pragma unroll
    for (int kk = 0; kk < KK; kk++) { float bv = eb[kk]; acc0[kk] = bv; acc1[kk] = bv; }

    const int h0 = 2 * hd0 - 1;
    const int w0 = 2 * wd0 - 1;
    const float* src = g_down + n * C_ * HW;

    for (int c = 0; c < 64; c++) {
        for (int idx = tid; idx < 33 * 33; idx += 128) {
            int r = idx / 33, cc = idx % 33;
            int h = h0 + r, w = w0 + cc;
            tile[r][cc] = (h >= 0 && h < H_ && w >= 0 && w < W_)
                          ? src[c * HW + h * W_ + w] : 0.f;
        }
        for (int idx = tid; idx < 225; idx += 128)
            ws[idx / 9][idx % 9] = ew[(idx / 9) * 576 + c * 9 + (idx % 9)];
        __syncthreads();

        float v0[9], v1[9];
#pragma unroll
        for (int r = 0; r < 3; r++)
#pragma unroll
            for (int s = 0; s < 3; s++) {
                v0[r * 3 + s] = tile[4 * ty + r][2 * tx + s];
                v1[r * 3 + s] = tile[4 * ty + 2 + r][2 * tx + s];
            }
#pragma unroll
        for (int kk = 0; kk < KK; kk++) {
            float s0 = 0.f, s1 = 0.f;
#pragma unroll
            for (int t = 0; t < 9; t++) {
                float wv = ws[kk][t];
                s0 += wv * v0[t];
                s1 += wv * v1[t];
            }
            acc0[kk] += s0; acc1[kk] += s1;
        }
        __syncthreads();
    }

    // softmax over 25, two rows
    const int wd = wd0 + tx;
    {
        int hd = hd0 + 2 * ty;
        float m = acc0[0];
#pragma unroll
        for (int kk = 1; kk < KK; kk++) m = fmaxf(m, acc0[kk]);
        float sum = 0.f;
#pragma unroll
        for (int kk = 0; kk < KK; kk++) { acc0[kk] = expf(acc0[kk] - m); sum += acc0[kk]; }
        float inv = 1.f / sum;
        float* dst = g_k + ((n * HD + hd) * WD + wd) * KK;
#pragma unroll
        for (int kk = 0; kk < KK; kk++) dst[kk] = acc0[kk] * inv;
    }
    {
        int hd = hd0 + 2 * ty + 1;
        float m = acc1[0];
#pragma unroll
        for (int kk = 1; kk < KK; kk++) m = fmaxf(m, acc1[kk]);
        float sum = 0.f;
#pragma unroll
        for (int kk = 0; kk < KK; kk++) { acc1[kk] = expf(acc1[kk] - m); sum += acc1[kk]; }
        float inv = 1.f / sum;
        float* dst = g_k + ((n * HD + hd) * WD + wd) * KK;
#pragma unroll
        for (int kk = 0; kk < KK; kk++) dst[kk] = acc1[kk] * inv;
    }
}

// ---------------------------------------------------------------------------
// Kernel 3: weighted 5x5 reassembly with row-major-reshape remap.
// For (c2, hd, wd): src pixel = x[c2>>2, (c2&3)*64 + (hd>>1)+di-2, 128*(hd&1)+wd+dj-2]
// Block = (n, c = c2>>2, 4-row hd tile, all 128 wd). 4 quadrant bands in smem.
// ---------------------------------------------------------------------------
__global__ void k_reasm(const float* __restrict__ x) {
    __shared__ float xt[4][6][260];
    const int n   = blockIdx.z;
    const int c   = blockIdx.y;
    const int hd0 = blockIdx.x * 4;
    const int tid = threadIdx.x;   // 256
    const float* src = x + (n * C_ + c) * HW;
    const int rbase = (hd0 >> 1) - 2;

    for (int idx = tid; idx < 4 * 6 * 260; idx += 256) {
        int q   = idx / (6 * 260);
        int rem = idx % (6 * 260);
        int rl  = rem / 260, cl = rem % 260;
        int h = q * 64 + rbase + rl;
        int w = cl - 2;
        xt[q][rl][cl] = (h >= 0 && h < H_ && w >= 0 && w < W_)
                        ? src[h * W_ + w] : 0.f;
    }
    __syncthreads();

    const int wd = tid & 127;
    const int ph = tid >> 7;   // 0..1
#pragma unroll
    for (int pp = 0; pp < 2; pp++) {
        const int dh = ph + 2 * pp;      // 0..3
        const int hd = hd0 + dh;
        const float* kp = g_k + ((n * HD + hd) * WD + wd) * KK;
        float kw[KK];
#pragma unroll
        for (int kk = 0; kk < KK; kk++) kw[kk] = __ldg(kp + kk);
        const int rl0  = dh >> 1;
        const int col0 = ((hd & 1) << 7) + wd;
#pragma unroll
        for (int q = 0; q < 4; q++) {
            float s = 0.f;
#pragma unroll
            for (int di = 0; di < 5; di++)
#pragma unroll
                for (int dj = 0; dj < 5; dj++)
                    s += kw[di * 5 + dj] * xt[q][rl0 + di][col0 + dj];
            g_reasm[((n * 256 + c * 4 + q) * HD + hd) * WD + wd] = s;
        }
    }
}

// ---------------------------------------------------------------------------
// Kernel 4: 1x1 conv 256->64 over (N,256,128,128). K-chunked GEMM,
// 64 pixels/block, 4x4 register tile.
// ---------------------------------------------------------------------------
__global__ void k_out(const float* __restrict__ w,
                      const float* __restrict__ b,
                      float* __restrict__ out) {
    __shared__ float Xs[64][65];   // [k][pixel]
    __shared__ float Ws[64][65];   // [k][cout]
    const int tid = threadIdx.x;
    const int n  = blockIdx.x >> 8;           // 256 blocks per n
    const int p0 = (blockIdx.x & 255) << 6;
    const int px = tid & 15, ch = tid >> 4;

    float acc[4][4];
#pragma unroll
    for (int j = 0; j < 4; j++) {
        float bv = b[ch + 16 * j];
#pragma unroll
        for (int i = 0; i < 4; i++) acc[i][j] = bv;
    }

    for (int kb = 0; kb < 4; kb++) {
        __syncthreads();
#pragma unroll
        for (int i = 0; i < 16; i++) {
            int idx = tid + i * 256;
            int r = idx >> 6, cc = idx & 63;
            Xs[r][cc] = g_reasm[(n * 256 + kb * 64 + r) * HWD + p0 + cc];
            Ws[cc][r] = w[r * 256 + kb * 64 + cc];   // w[cout][256]
        }
        __syncthreads();
#pragma unroll 8
        for (int kc = 0; kc < 64; kc++) {
            float xv[4], wv[4];
#pragma unroll
            for (int i = 0; i < 4; i++) xv[i] = Xs[kc][px + 16 * i];
#pragma unroll
            for (int j = 0; j < 4; j++) wv[j] = Ws[kc][ch + 16 * j];
#pragma unroll
            for (int i = 0; i < 4; i++)
#pragma unroll
                for (int j = 0; j < 4; j++) acc[i][j] += xv[i] * wv[j];
        }
    }

#pragma unroll
    for (int j = 0; j < 4; j++)
#pragma unroll
        for (int i = 0; i < 4; i++)
            out[(n * 64 + ch + 16 * j) * HWD + p0 + px + 16 * i] = acc[i][j];
}

// ---------------------------------------------------------------------------
extern "C" void kernel_launch(void* const* d_in, const int* in_sizes, int n_in,
                              void* d_out, int out_size) {
    const float* x      = (const float*)d_in[0];
    const float* down_w = (const float*)d_in[1];
    const float* down_b = (const float*)d_in[2];
    const float* enc_w  = (const float*)d_in[3];
    const float* enc_b  = (const float*)d_in[4];
    const float* out_w  = (const float*)d_in[5];
    const float* out_b  = (const float*)d_in[6];
    float* out = (float*)d_out;

    k_down<<<2048, 256>>>(x, down_w, down_b);

    dim3 g2(8, 8, 2);
    k_enc<<<g2, 128>>>(enc_w, enc_b);

    dim3 g3(32, 64, 2);
    k_reasm<<<g3, 256>>>(x);

    k_out<<<512, 256>>>(out_w, out_b, out);
}